// round 17
// baseline (speedup 1.0000x reference)
#include <cuda_runtime.h>
#include <cuda_fp16.h>
#include <stdint.h>

#define BB   512
#define TW   512
#define TCC  512
#define INP  16
#define HID  64
#define FD   8
#define SPB  4
#define NT   512
#define HPAD 68
#define GPAD 260
#define UXS  24    // uf0 stride in halfs (x/dec-input: 16 + pad) -> banks 12g+q, conflict-free
#define UHS  72    // h0buf/h1buf stride in halfs (64 + pad) -> banks 4g+q, conflict-free

__device__ __forceinline__ float tanha(float x) {
    float r; asm("tanh.approx.f32 %0, %1;" : "=f"(r) : "f"(x)); return r;
}
__device__ __forceinline__ float sigf(float x) {
    return fmaf(tanha(0.5f * x), 0.5f, 0.5f);
}
__device__ __forceinline__ uint32_t h2(float a, float b) {
    __half2 h = __floats2half2_rn(a, b);
    return *reinterpret_cast<uint32_t*>(&h);
}
__device__ __forceinline__ void mma16816(
    float* d, const uint32_t* a, uint32_t b0, uint32_t b1)
{
    asm("mma.sync.aligned.m16n8k16.row.col.f32.f16.f16.f32 "
        "{%0,%1,%2,%3},{%4,%5,%6,%7},{%8,%9},{%0,%1,%2,%3};"
        : "+f"(d[0]), "+f"(d[1]), "+f"(d[2]), "+f"(d[3])
        : "r"(a[0]), "r"(a[1]), "r"(a[2]), "r"(a[3]), "r"(b0), "r"(b1));
}

__global__ __launch_bounds__(NT, 1) void lstm_ar_kernel(
    const float* __restrict__ x,     const int* __restrict__ lenx_g,
    const float* __restrict__ ctx,   const int* __restrict__ lctx_g,
    const float* __restrict__ Wih0,  const float* __restrict__ Whh0,
    const float* __restrict__ bih0,  const float* __restrict__ bhh0,
    const float* __restrict__ Wih1,  const float* __restrict__ Whh1,
    const float* __restrict__ bih1,  const float* __restrict__ bhh1,
    const float* __restrict__ Wd,    const float* __restrict__ bd,
    float* __restrict__ out)
{
    __shared__ __align__(16) __half uf0[8][UXS];       // x / dec-input per sample
    __shared__ __align__(16) __half h0buf[2][8][UHS];  // h0 double buffer (parity)
    __shared__ __align__(16) __half h1buf[8][UHS];     // h1
    __shared__ __align__(16) float g0sh[SPB][GPAD];
    __shared__ __align__(16) float g1sh[SPB][GPAD];
    __shared__ __align__(16) float h1sh[SPB][HPAD];    // fp32 h1 for projections
    __shared__ float wdsh[FD * 65];
    __shared__ float bdsh[FD];
    __shared__ float elem[SPB][FD];
    __shared__ int   lens[SPB];
    __shared__ int   ldec[SPB];

    const int tid = threadIdx.x;
    const int s0  = blockIdx.x * SPB;

    // ---- fill invalid output rows with -999 ----
    {
        const float4 m = make_float4(-999.f, -999.f, -999.f, -999.f);
        #pragma unroll
        for (int s = 0; s < SPB; s++) {
            int lc = lctx_g[s0 + s];
            float4* po = (float4*)(out + (size_t)(s0 + s) * TCC * FD);
            for (int i = lc * 2 + tid; i < (TCC * FD) / 4; i += NT) po[i] = m;
        }
    }
    // ---- zero activation buffers ----
    {
        __half z = __float2half(0.f);
        __half* p0 = &uf0[0][0];
        for (int i = tid; i < 8 * UXS; i += NT) p0[i] = z;
        __half* ph = &h0buf[0][0][0];
        for (int i = tid; i < 2 * 8 * UHS; i += NT) ph[i] = z;
        __half* p1 = &h1buf[0][0];
        for (int i = tid; i < 8 * UHS; i += NT) p1[i] = z;
    }
    if (tid < SPB) { lens[tid] = lenx_g[s0 + tid]; ldec[tid] = lctx_g[s0 + tid] - 1; }
    for (int i = tid; i < FD * HID; i += NT) wdsh[(i >> 6) * 65 + (i & 63)] = Wd[i];
    if (tid < FD) bdsh[tid] = bd[tid];
    __syncthreads();

    const int w = tid >> 5, lane = tid & 31;
    const int g = lane >> 2, q = lane & 3;
    const int c0 = 2 * q;
    const int Tenc = max(max(lens[0], lens[1]), max(lens[2], lens[3]));
    const int Tdec = max(max(ldec[0], ldec[1]), max(ldec[2], ldec[3]));

    const bool isL0 = (w < 8);
    // tiles: each engine warp owns 2 M-tiles (rows 32wj.. / +16)
    const int wj  = isL0 ? w : (w - 8);
    const int rA0 = 32 * wj + g,      rB0 = rA0 + 8;
    const int rA1 = 32 * wj + 16 + g, rB1 = rA1 + 8;

    // A fragments (arm-scoped sizes via max array; only owning arm populated)
    uint32_t f0[2][5][4];
    uint32_t f1[2][8][4];
    float bAr[2], bBr[2];
    if (isL0) {
        #pragma unroll
        for (int j = 0; j < 2; j++) {
            int rA = j ? rA1 : rA0, rB = j ? rB1 : rB0;
            f0[j][0][0] = h2(Wih0[rA * INP + c0],     Wih0[rA * INP + c0 + 1]);
            f0[j][0][1] = h2(Wih0[rB * INP + c0],     Wih0[rB * INP + c0 + 1]);
            f0[j][0][2] = h2(Wih0[rA * INP + c0 + 8], Wih0[rA * INP + c0 + 9]);
            f0[j][0][3] = h2(Wih0[rB * INP + c0 + 8], Wih0[rB * INP + c0 + 9]);
            #pragma unroll
            for (int kt = 1; kt < 5; kt++) {
                int kb = (kt - 1) * 16;
                f0[j][kt][0] = h2(Whh0[rA * HID + kb + c0],     Whh0[rA * HID + kb + c0 + 1]);
                f0[j][kt][1] = h2(Whh0[rB * HID + kb + c0],     Whh0[rB * HID + kb + c0 + 1]);
                f0[j][kt][2] = h2(Whh0[rA * HID + kb + c0 + 8], Whh0[rA * HID + kb + c0 + 9]);
                f0[j][kt][3] = h2(Whh0[rB * HID + kb + c0 + 8], Whh0[rB * HID + kb + c0 + 9]);
            }
            bAr[j] = bih0[rA] + bhh0[rA]; bBr[j] = bih0[rB] + bhh0[rB];
        }
    } else {
        #pragma unroll
        for (int j = 0; j < 2; j++) {
            int rA = j ? rA1 : rA0, rB = j ? rB1 : rB0;
            #pragma unroll
            for (int kt = 0; kt < 4; kt++) {
                int kb = kt * 16;
                f1[j][kt][0] = h2(Wih1[rA * HID + kb + c0],     Wih1[rA * HID + kb + c0 + 1]);
                f1[j][kt][1] = h2(Wih1[rB * HID + kb + c0],     Wih1[rB * HID + kb + c0 + 1]);
                f1[j][kt][2] = h2(Wih1[rA * HID + kb + c0 + 8], Wih1[rA * HID + kb + c0 + 9]);
                f1[j][kt][3] = h2(Wih1[rB * HID + kb + c0 + 8], Wih1[rB * HID + kb + c0 + 9]);
            }
            #pragma unroll
            for (int kt = 4; kt < 8; kt++) {
                int kb = (kt - 4) * 16;
                f1[j][kt][0] = h2(Whh1[rA * HID + kb + c0],     Whh1[rA * HID + kb + c0 + 1]);
                f1[j][kt][1] = h2(Whh1[rB * HID + kb + c0],     Whh1[rB * HID + kb + c0 + 1]);
                f1[j][kt][2] = h2(Whh1[rA * HID + kb + c0 + 8], Whh1[rA * HID + kb + c0 + 9]);
                f1[j][kt][3] = h2(Whh1[rB * HID + kb + c0 + 8], Whh1[rB * HID + kb + c0 + 9]);
            }
            bAr[j] = bih1[rA] + bhh1[rA]; bBr[j] = bih1[rB] + bhh1[rB];
        }
    }

    // combine ownership: L0 warps (tid<256) own layer-0 unit; L1 warps layer-1
    const int cu = isL0 ? tid : (tid - 256);
    const int cs = cu >> 6, cj = cu & 63;
    const int myLe = lens[cs], myLd = ldec[cs];
    float cst = 0.f, hreg = 0.f;

    const int ps = tid >> 4, pk = tid & 15;  // x prefetch (tid < 64, L0 warps 0-1)
    const int ds = tid >> 3, dk = tid & 7;   // ctx / projection (tid < 32)

    auto gemm0 = [&](int p) {   // g0 <- Wa*x + Wb*h0[p]
        float dA0[4] = {bAr[0], bAr[0], bBr[0], bBr[0]};
        float dA1[4] = {bAr[1], bAr[1], bBr[1], bBr[1]};
        float dB0[4] = {0.f, 0.f, 0.f, 0.f};
        float dB1[4] = {0.f, 0.f, 0.f, 0.f};
        {
            uint32_t bv0 = *(const uint32_t*)&uf0[g][c0];
            uint32_t bv1 = *(const uint32_t*)&uf0[g][c0 + 8];
            mma16816(dA0, f0[0][0], bv0, bv1);
            mma16816(dA1, f0[1][0], bv0, bv1);
        }
        #pragma unroll
        for (int kt = 1; kt < 3; kt++) {
            uint32_t bv0 = *(const uint32_t*)&h0buf[p][g][(kt - 1) * 16 + c0];
            uint32_t bv1 = *(const uint32_t*)&h0buf[p][g][(kt - 1) * 16 + c0 + 8];
            mma16816(dA0, f0[0][kt], bv0, bv1);
            mma16816(dA1, f0[1][kt], bv0, bv1);
        }
        #pragma unroll
        for (int kt = 3; kt < 5; kt++) {
            uint32_t bv0 = *(const uint32_t*)&h0buf[p][g][(kt - 1) * 16 + c0];
            uint32_t bv1 = *(const uint32_t*)&h0buf[p][g][(kt - 1) * 16 + c0 + 8];
            mma16816(dB0, f0[0][kt], bv0, bv1);
            mma16816(dB1, f0[1][kt], bv0, bv1);
        }
        if (q < 2) {
            int sA = 2 * q, sB = 2 * q + 1;
            g0sh[sA][rA0] = dA0[0] + dB0[0]; g0sh[sB][rA0] = dA0[1] + dB0[1];
            g0sh[sA][rB0] = dA0[2] + dB0[2]; g0sh[sB][rB0] = dA0[3] + dB0[3];
            g0sh[sA][rA1] = dA1[0] + dB1[0]; g0sh[sB][rA1] = dA1[1] + dB1[1];
            g0sh[sA][rB1] = dA1[2] + dB1[2]; g0sh[sB][rB1] = dA1[3] + dB1[3];
        }
    };
    auto gemm1 = [&](int p) {   // g1 <- Wc*h0[p] + Wd*h1
        float eA0[4] = {bAr[0], bAr[0], bBr[0], bBr[0]};
        float eA1[4] = {bAr[1], bAr[1], bBr[1], bBr[1]};
        float eB0[4] = {0.f, 0.f, 0.f, 0.f};
        float eB1[4] = {0.f, 0.f, 0.f, 0.f};
        #pragma unroll
        for (int kt = 0; kt < 4; kt++) {
            uint32_t bv0 = *(const uint32_t*)&h0buf[p][g][kt * 16 + c0];
            uint32_t bv1 = *(const uint32_t*)&h0buf[p][g][kt * 16 + c0 + 8];
            mma16816(eA0, f1[0][kt], bv0, bv1);
            mma16816(eA1, f1[1][kt], bv0, bv1);
        }
        #pragma unroll
        for (int kt = 4; kt < 8; kt++) {
            uint32_t bv0 = *(const uint32_t*)&h1buf[g][(kt - 4) * 16 + c0];
            uint32_t bv1 = *(const uint32_t*)&h1buf[g][(kt - 4) * 16 + c0 + 8];
            mma16816(eB0, f1[0][kt], bv0, bv1);
            mma16816(eB1, f1[1][kt], bv0, bv1);
        }
        if (q < 2) {
            int sA = 2 * q, sB = 2 * q + 1;
            g1sh[sA][rA0] = eA0[0] + eB0[0]; g1sh[sB][rA0] = eA0[1] + eB0[1];
            g1sh[sA][rB0] = eA0[2] + eB0[2]; g1sh[sB][rB0] = eA0[3] + eB0[3];
            g1sh[sA][rA1] = eA1[0] + eB1[0]; g1sh[sB][rA1] = eA1[1] + eB1[1];
            g1sh[sA][rB1] = eA1[2] + eB1[2]; g1sh[sB][rB1] = eA1[3] + eB1[3];
        }
    };
    auto comb0 = [&](bool active, int slot) {   // h0(u); always-write held value
        if (active) {
            float fi = sigf(g0sh[cs][cj]);
            float ff = sigf(g0sh[cs][64 + cj]);
            float fg = tanha(g0sh[cs][128 + cj]);
            float fo = sigf(g0sh[cs][192 + cj]);
            cst = ff * cst + fi * fg;
            hreg = fo * tanha(cst);
        }
        h0buf[slot][cs][cj] = __float2half(hreg);
    };
    auto comb1 = [&](bool active) {   // h1(v); always-write
        if (active) {
            float fi = sigf(g1sh[cs][cj]);
            float ff = sigf(g1sh[cs][64 + cj]);
            float fg = tanha(g1sh[cs][128 + cj]);
            float fo = sigf(g1sh[cs][192 + cj]);
            cst = ff * cst + fi * fg;
            hreg = fo * tanha(cst);
        }
        h1buf[cs][cj] = __float2half(hreg);
        h1sh[cs][cj]  = hreg;
    };
    auto proj = [&](int row) {   // tid < 32 only
        float a0 = bdsh[dk], a1 = 0.f, a2 = 0.f, a3 = 0.f;
        #pragma unroll
        for (int j = 0; j < HID; j += 4) {
            a0 = fmaf(wdsh[dk * 65 + j    ], h1sh[ds][j    ], a0);
            a1 = fmaf(wdsh[dk * 65 + j + 1], h1sh[ds][j + 1], a1);
            a2 = fmaf(wdsh[dk * 65 + j + 2], h1sh[ds][j + 2], a2);
            a3 = fmaf(wdsh[dk * 65 + j + 3], h1sh[ds][j + 3], a3);
        }
        out[((size_t)(s0 + ds) * TCC + row) * FD + dk] = (a0 + a1) + (a2 + a3);
    };

    // ================= encoder prologue =================
    if (tid < 64) uf0[ps][pk] = __float2half(x[((size_t)(s0 + ps) * TW) * INP + pk]);
    __syncthreads();
    if (isL0) gemm0(1);                       // g0(0); h0 init 0 (both slots zero)
    float xn = 0.f;
    if (tid < 64) xn = x[((size_t)(s0 + ps) * TW + min(1, TW - 1)) * INP + pk];
    __syncthreads();
    if (isL0) comb0(true, 0);                 // h0(0) -> slot 0 (lens >= 2)
    if (tid < 64) {
        uf0[ps][pk] = __float2half(xn);       // x(1)
        xn = x[((size_t)(s0 + ps) * TW + min(2, TW - 1)) * INP + pk];
    }
    __syncthreads();

    // ================= encoder loop =================
    for (int t = 0; t < Tenc; t++) {
        // phase 1: gemm0 -> g0(t+1)  ||  comb1 -> h1(t-1)
        if (isL0) gemm0(t & 1);
        else if (t > 0) comb1((t - 1) < myLe);
        __syncthreads();
        // phase 2: comb0 -> h0(t+1)  ||  gemm1 -> g1(t)
        if (isL0) {
            comb0((t + 1) < myLe, (t + 1) & 1);
            if (tid < 64) {
                uf0[ps][pk] = __float2half(xn);   // x(t+2)
                int tt = (t + 3 < TW) ? t + 3 : TW - 1;
                xn = x[((size_t)(s0 + ps) * TW + tt) * INP + pk];
            }
        } else {
            gemm1(t & 1);
        }
        __syncthreads();
    }
    // epilogue: comb1(Tenc-1)
    if (!isL0) comb1((Tenc - 1) < myLe);
    __syncthreads();

    // ================= element = h1 @ Wd.T + bd =================
    if (tid < 32) {
        float a0 = bdsh[dk], a1 = 0.f, a2 = 0.f, a3 = 0.f;
        #pragma unroll
        for (int j = 0; j < HID; j += 4) {
            a0 = fmaf(wdsh[dk * 65 + j    ], h1sh[ds][j    ], a0);
            a1 = fmaf(wdsh[dk * 65 + j + 1], h1sh[ds][j + 1], a1);
            a2 = fmaf(wdsh[dk * 65 + j + 2], h1sh[ds][j + 2], a2);
            a3 = fmaf(wdsh[dk * 65 + j + 3], h1sh[ds][j + 3], a3);
        }
        float e = (a0 + a1) + (a2 + a3);
        elem[ds][dk] = e;
        out[(size_t)(s0 + ds) * TCC * FD + dk] = e;   // row 0
    }
    __syncthreads();

    // ================= decoder prologue =================
    if (tid < 64 && pk < 8) uf0[ps][pk] = __float2half(elem[ps][pk]);
    if (tid < 32) uf0[ds][8 + dk] = __float2half(ctx[((size_t)(s0 + ds) * TCC) * FD + dk]);
    if (isL0) h0buf[1][cs][cj] = __float2half(hreg);   // h0(enc final) as "h0(-1)"
    __syncthreads();
    if (isL0) gemm0(1);                       // g0_dec(0)
    float cn = 0.f;
    if (tid < 32) cn = ctx[((size_t)(s0 + ds) * TCC + min(1, TCC - 1)) * FD + dk];
    __syncthreads();
    if (isL0) comb0(0 < myLd, 0);             // h0_dec(0) -> slot 0
    if (tid < 32) {
        uf0[ds][8 + dk] = __float2half(cn);   // ctx(1)
        cn = ctx[((size_t)(s0 + ds) * TCC + min(2, TCC - 1)) * FD + dk];
    }
    __syncthreads();

    // ================= decoder loop =================
    for (int t = 0; t < Tdec; t++) {
        // phase 1: gemm0 -> g0d(t+1)  ||  comb1 -> h1d(t-1)
        if (isL0) gemm0(t & 1);
        else if (t > 0) comb1((t - 1) < myLd);
        __syncthreads();
        // phase 2: comb0 -> h0d(t+1) + proj(t)  ||  gemm1 -> g1d(t)
        if (isL0) {
            comb0((t + 1) < myLd, (t + 1) & 1);
            if (tid < 32) {
                uf0[ds][8 + dk] = __float2half(cn);   // ctx(t+2)
                int tt = (t + 3 < TCC) ? t + 3 : TCC - 1;
                cn = ctx[((size_t)(s0 + ds) * TCC + tt) * FD + dk];
                if (t > 0 && (t - 1) < ldec[ds]) proj(t);
            }
        } else {
            gemm1(t & 1);
        }
        __syncthreads();
    }
    // epilogue: comb1(Tdec-1), then final projection
    if (!isL0) comb1((Tdec - 1) < myLd);
    __syncthreads();
    if (tid < 32 && (Tdec - 1) < ldec[ds]) proj(Tdec);
}

extern "C" void kernel_launch(void* const* d_in, const int* in_sizes, int n_in,
                              void* d_out, int out_size) {
    (void)in_sizes; (void)n_in; (void)out_size;
    lstm_ar_kernel<<<BB / SPB, NT>>>(
        (const float*)d_in[0],  (const int*)d_in[1],
        (const float*)d_in[2],  (const int*)d_in[3],
        (const float*)d_in[4],  (const float*)d_in[5],
        (const float*)d_in[6],  (const float*)d_in[7],
        (const float*)d_in[8],  (const float*)d_in[9],
        (const float*)d_in[10], (const float*)d_in[11],
        (const float*)d_in[12], (const float*)d_in[13],
        (float*)d_out);
}